// round 16
// baseline (speedup 1.0000x reference)
#include <cuda_runtime.h>
#include <cuda_bf16.h>
#include <math.h>
#include <stdint.h>

#define EDIM 1024
#define BDIM 4
#define HDIM 16
#define DHD 64
#define LQ 512
#define SK 1024
#define BH 64   // BDIM*HDIM

// ======================= helpers =======================
__device__ __forceinline__ uint32_t smem_to_u32(const void* smem_ptr) {
    uint32_t addr;
    asm("{ .reg .u64 tmp; cvta.to.shared.u64 tmp, %1; cvt.u32.u64 %0, tmp; }"
        : "=r"(addr) : "l"(smem_ptr));
    return addr;
}
__device__ __forceinline__ void ldm_x4(uint32_t* r, uint32_t addr) {
    asm volatile("ldmatrix.sync.aligned.m8n8.x4.shared.b16 {%0,%1,%2,%3}, [%4];"
        : "=r"(r[0]), "=r"(r[1]), "=r"(r[2]), "=r"(r[3]) : "r"(addr));
}
__device__ __forceinline__ void ldm_x4_t(uint32_t* r, uint32_t addr) {
    asm volatile("ldmatrix.sync.aligned.m8n8.x4.trans.shared.b16 {%0,%1,%2,%3}, [%4];"
        : "=r"(r[0]), "=r"(r[1]), "=r"(r[2]), "=r"(r[3]) : "r"(addr));
}
__device__ __forceinline__ void mma16816(float* d, const uint32_t* a, uint32_t b0, uint32_t b1) {
    asm volatile("mma.sync.aligned.m16n8k16.row.col.f32.bf16.bf16.f32 "
        "{%0,%1,%2,%3}, {%4,%5,%6,%7}, {%8,%9}, {%0,%1,%2,%3};"
        : "+f"(d[0]), "+f"(d[1]), "+f"(d[2]), "+f"(d[3])
        : "r"(a[0]), "r"(a[1]), "r"(a[2]), "r"(a[3]), "r"(b0), "r"(b1));
}
#define CP_ASYNC16(saddr, gptr) \
    asm volatile("cp.async.cg.shared.global [%0], [%1], 16;" :: "r"(saddr), "l"(gptr))
#define CP_COMMIT()  asm volatile("cp.async.commit_group;" ::: "memory")
#define CP_WAIT(N)   asm volatile("cp.async.wait_group %0;" :: "n"(N) : "memory")

// ---- MUFU-free math ----
__device__ __forceinline__ float fast_sqrt(float x) {
    float r = __int_as_float(0x5f3759df - (__float_as_int(x) >> 1));
    r = r * fmaf(-0.5f * x * r, r, 1.5f);
    r = r * fmaf(-0.5f * x * r, r, 1.5f);
    r = r * fmaf(-0.5f * x * r, r, 1.5f);
    return x * r;
}
__device__ __forceinline__ float fast_exp(float x) {
    float y = x * 1.44269504f;
    y = fmaxf(fminf(y, 126.0f), -125.0f);
    float t = y + 12582912.f;
    int n = __float_as_int(t) - 0x4B400000;
    float f = y - (t - 12582912.f);
    float p = 1.33335581e-3f;
    p = fmaf(p, f, 9.61812910e-3f);
    p = fmaf(p, f, 5.55041086e-2f);
    p = fmaf(p, f, 2.40226507e-1f);
    p = fmaf(p, f, 6.93147181e-1f);
    p = fmaf(p, f, 1.0f);
    return __int_as_float(__float_as_int(p) + (n << 23));
}
__device__ __forceinline__ float fast_rcp(float x) {
    float r = __int_as_float(0x7EF311C3 - __float_as_int(x));
    r = r * (2.0f - x * r);
    r = r * (2.0f - x * r);
    r = r * (2.0f - x * r);
    return r;
}
__device__ __forceinline__ float fast_sigmoid(float x) {
    return fast_rcp(1.0f + fast_exp(-x));
}

// ---------------- scratch ----------------
__device__ float g_G1h[BH*LQ*DHD];
__device__ float g_G2h[BH*LQ*DHD];
__device__ float g_ll [BH*LQ];
__device__ float g_vv [BH*SK];
__device__ float g_aa [BH*SK];
__device__ float g_va [BH*SK];
__device__ float g_Attn[BH*LQ*SK];

__device__ __align__(16) __nv_bfloat16 g_q_hi [BH*LQ*DHD];
__device__ __align__(16) __nv_bfloat16 g_q_lo [BH*LQ*DHD];
__device__ __align__(16) __nv_bfloat16 g_k1_hi[BH*SK*DHD];
__device__ __align__(16) __nv_bfloat16 g_k1_lo[BH*SK*DHD];
__device__ __align__(16) __nv_bfloat16 g_k2_hi[BH*SK*DHD];
__device__ __align__(16) __nv_bfloat16 g_k2_lo[BH*SK*DHD];
__device__ __align__(16) __nv_bfloat16 g_v1_hi[BH*SK*DHD];
__device__ __align__(16) __nv_bfloat16 g_v1_lo[BH*SK*DHD];
__device__ __align__(16) __nv_bfloat16 g_v2_hi[BH*SK*DHD];
__device__ __align__(16) __nv_bfloat16 g_v2_lo[BH*SK*DHD];
__device__ __align__(16) __nv_bfloat16 g_at_hi[BH*LQ*SK];
__device__ __align__(16) __nv_bfloat16 g_at_lo[BH*LQ*SK];
__device__ __align__(16) __nv_bfloat16 g_xq_hi[2048*1024];
__device__ __align__(16) __nv_bfloat16 g_xq_lo[2048*1024];
__device__ __align__(16) __nv_bfloat16 g_m1_hi[4096*1024];
__device__ __align__(16) __nv_bfloat16 g_m1_lo[4096*1024];
__device__ __align__(16) __nv_bfloat16 g_m2_hi[4096*1024];
__device__ __align__(16) __nv_bfloat16 g_m2_lo[4096*1024];
__device__ __align__(16) __nv_bfloat16 g_cb_hi[2048*1024];
__device__ __align__(16) __nv_bfloat16 g_cb_lo[2048*1024];
__device__ __align__(16) __nv_bfloat16 g_wt_hi[8*1024*1024];
__device__ __align__(16) __nv_bfloat16 g_wt_lo[8*1024*1024];

// ---------------- merged preprocessing: input split + weight transpose/split ----------------
struct WPtrs { const float* p[8]; };

__global__ void k_prep(const float* __restrict__ q, const float* __restrict__ m1,
                       const float* __restrict__ m2, WPtrs wp,
                       __nv_bfloat16* __restrict__ qhi, __nv_bfloat16* __restrict__ qlo,
                       __nv_bfloat16* __restrict__ m1hi, __nv_bfloat16* __restrict__ m1lo,
                       __nv_bfloat16* __restrict__ m2hi, __nv_bfloat16* __restrict__ m2lo,
                       __nv_bfloat16* __restrict__ ThiAll, __nv_bfloat16* __restrict__ TloAll)
{
    __shared__ float t[32][33];
    const int bxb = blockIdx.x;
    if (bxb < 10240) {
        // ---- input split ----
        int i = bxb * 256 + threadIdx.x;
        const float* src; __nv_bfloat16 *hi, *lo; int off;
        if (i < 512*1024)        { src = q;  hi = qhi;  lo = qlo;  off = i; }
        else if (i < 1536*1024)  { src = m1; hi = m1hi; lo = m1lo; off = i - 512*1024; }
        else                     { src = m2; hi = m2hi; lo = m2lo; off = i - 1536*1024; }
        float4 v = ((const float4*)src)[off];
        __nv_bfloat16 h0 = __float2bfloat16(v.x), h1 = __float2bfloat16(v.y);
        __nv_bfloat16 h2 = __float2bfloat16(v.z), h3 = __float2bfloat16(v.w);
        __nv_bfloat16 l0 = __float2bfloat16(v.x - __bfloat162float(h0));
        __nv_bfloat16 l1 = __float2bfloat16(v.y - __bfloat162float(h1));
        __nv_bfloat16 l2 = __float2bfloat16(v.z - __bfloat162float(h2));
        __nv_bfloat16 l3 = __float2bfloat16(v.w - __bfloat162float(h3));
        __nv_bfloat162* hp = (__nv_bfloat162*)(hi + (size_t)off * 4);
        __nv_bfloat162* lp = (__nv_bfloat162*)(lo + (size_t)off * 4);
        hp[0] = __nv_bfloat162(h0, h1); hp[1] = __nv_bfloat162(h2, h3);
        lp[0] = __nv_bfloat162(l0, l1); lp[1] = __nv_bfloat162(l2, l3);
    } else {
        // ---- weight transpose + split: W [k][n] -> WT hi/lo [n][k] ----
        int idx = bxb - 10240;                 // 0..8191
        int wi = idx >> 10;                    // weight index 0..7
        int rem = idx & 1023;
        int bn = (rem & 31) << 5;              // n-base
        int bk = (rem >> 5) << 5;              // k-base
        const float* W = wp.p[wi];
        __nv_bfloat16* Thi = ThiAll + (size_t)wi * 1024 * 1024;
        __nv_bfloat16* Tlo = TloAll + (size_t)wi * 1024 * 1024;
        const int x = threadIdx.x & 31, y = threadIdx.x >> 5;   // 32 x 8
#pragma unroll
        for (int i = 0; i < 32; i += 8)
            t[y + i][x] = W[(size_t)(bk + y + i) * EDIM + bn + x];
        __syncthreads();
#pragma unroll
        for (int i = 0; i < 32; i += 8) {
            float v = t[x][y + i];
            __nv_bfloat16 h = __float2bfloat16(v);
            __nv_bfloat16 l = __float2bfloat16(v - __bfloat162float(h));
            size_t o = (size_t)(bn + y + i) * EDIM + bk + x;
            Thi[o] = h; Tlo[o] = l;
        }
    }
}

// ================== batched warp-MMA bf16x3 GEMM (up to 8 z-slices) ==================
struct GemmBatch {
    const __nv_bfloat16* Ahi[8];
    const __nv_bfloat16* Alo[8];
    const __nv_bfloat16* Bhi[8];
    const __nv_bfloat16* Blo[8];
    const float* bias[8];
    float* outF[8];
    __nv_bfloat16* outHi[8];
    __nv_bfloat16* outLo[8];
    float scale[8];
    int   mode[8];
    int   rows[8];
    int   npos[8];
};

template <int TM>
__global__ void __launch_bounds__(256, (TM == 64 ? 3 : 2))
gemm_mma(GemmBatch gb)
{
    constexpr int ATILE = TM * 64;
    constexpr int BTILE = 128 * 64;
    constexpr int STAGE = 2 * ATILE + 2 * BTILE;
    constexpr int MW = TM / 32;
    constexpr int WN = 128 / (8 / MW);
    constexpr int NT = WN / 8;
    constexpr int ACH = TM * 4;
    constexpr int CH = (2 * ACH + 1024) / 256;
    constexpr int NITER = 32;

    const int z = blockIdx.z;
    const int m0 = blockIdx.y * TM, n0 = blockIdx.x << 7;
    if (m0 >= gb.rows[z]) return;
    const float* __restrict__ bias = gb.bias[z];
    const float scale = gb.scale[z];
    const int mode = gb.mode[z];
    const int npos = gb.npos[z];

    extern __shared__ char smem[];
    const uint32_t sb = (smem_to_u32(smem) + 63u) & ~63u;
    const int tid = threadIdx.x;
    const int wid = tid >> 5, lane = tid & 31;
    const int wm = (wid % MW) << 5;
    const int wn = (wid / MW) * WN;

    float acc[2][NT][4];
#pragma unroll
    for (int i = 0; i < 2; i++)
#pragma unroll
        for (int j = 0; j < NT; j++)
#pragma unroll
            for (int q = 0; q < 4; q++) acc[i][j][q] = 0.f;

    const __nv_bfloat16* gptr[CH];
    uint32_t soff[CH];
#pragma unroll
    for (int i = 0; i < CH; i++) {
        int cid = (i << 8) + tid;
        const __nv_bfloat16* gp; int rowbase; uint32_t toff; int local;
        if (cid < ACH)               { gp = gb.Ahi[z]; rowbase = m0; toff = 0;                 local = cid; }
        else if (cid < 2 * ACH)      { gp = gb.Alo[z]; rowbase = m0; toff = ATILE;             local = cid - ACH; }
        else if (cid < 2 * ACH + 512){ gp = gb.Bhi[z]; rowbase = n0; toff = 2 * ATILE;         local = cid - 2 * ACH; }
        else                         { gp = gb.Blo[z]; rowbase = n0; toff = 2 * ATILE + BTILE; local = cid - 2 * ACH - 512; }
        int r = local >> 2, c = local & 3;
        gptr[i] = gp + (((size_t)(rowbase + r)) << 10) + (c << 3);
        soff[i] = toff + (uint32_t)(r << 6) + (uint32_t)((c ^ ((r >> 1) & 3)) << 4);
    }
    auto load_stage = [&](int s) {
        uint32_t base = sb + (uint32_t)s * STAGE;
#pragma unroll
        for (int i = 0; i < CH; i++) {
            CP_ASYNC16(base + soff[i], gptr[i]);
            gptr[i] += 32;
        }
        CP_COMMIT();
    };

    load_stage(0);
    load_stage(1);

    uint32_t lA[2], lB[NT / 2];
#pragma unroll
    for (int mt = 0; mt < 2; mt++) {
        int r = wm + mt * 16 + (lane & 15);
        lA[mt] = (uint32_t)(r << 6) + (uint32_t)((((lane >> 4) ^ ((r >> 1) & 3))) << 4);
    }
#pragma unroll
    for (int ng = 0; ng < NT / 2; ng++) {
        int r = wn + ng * 16 + (lane & 15);
        lB[ng] = 2u * ATILE + (uint32_t)(r << 6) + (uint32_t)((((lane >> 4) ^ ((r >> 1) & 3))) << 4);
    }

    for (int it = 0; it < NITER; it++) {
        const int s = it % 3;
        CP_WAIT(1);
        __syncthreads();
        if (it + 2 < NITER) load_stage((it + 2) % 3);
        else CP_COMMIT();

        const uint32_t st = sb + (uint32_t)s * STAGE;
#pragma unroll
        for (int kk = 0; kk < 2; kk++) {
            const uint32_t xv = (uint32_t)(kk << 5);
            uint32_t ahi[2][4], alo[2][4];
#pragma unroll
            for (int mt = 0; mt < 2; mt++) {
                uint32_t a = (st + lA[mt]) ^ xv;
                ldm_x4(ahi[mt], a);
                ldm_x4(alo[mt], a + ATILE);
            }
#pragma unroll
            for (int ng = 0; ng < NT / 2; ng++) {
                uint32_t bhi[4], blo[4];
                uint32_t b = (st + lB[ng]) ^ xv;
                ldm_x4(bhi, b);
                ldm_x4(blo, b + BTILE);
#pragma unroll
                for (int mt = 0; mt < 2; mt++)
#pragma unroll
                    for (int sel = 0; sel < 2; sel++) {
                        const int nt = ng * 2 + sel;
                        mma16816(acc[mt][nt], ahi[mt], bhi[sel], bhi[sel + 2]);
                        mma16816(acc[mt][nt], ahi[mt], blo[sel], blo[sel + 2]);
                        mma16816(acc[mt][nt], alo[mt], bhi[sel], bhi[sel + 2]);
                    }
            }
        }
    }
    CP_WAIT(0);

    // ---- epilogue ----
    const int qr = lane >> 2, qc = (lane & 3) << 1;
#pragma unroll
    for (int mt = 0; mt < 2; mt++) {
#pragma unroll
        for (int nt = 0; nt < NT; nt++) {
#pragma unroll
            for (int half = 0; half < 2; half++) {
                int row = m0 + wm + mt * 16 + qr + (half << 3);
                int col = n0 + wn + nt * 8 + qc;
                float v0 = (acc[mt][nt][half * 2 + 0] + bias[col])     * scale;
                float v1 = (acc[mt][nt][half * 2 + 1] + bias[col + 1]) * scale;
                if (mode == 2) {
                    *(float2*)&gb.outF[z][(size_t)row * EDIM + col] = make_float2(v0, v1);
                } else {
                    int pos = row >> 2;              // B = 4
                    int b = row & 3;
                    int h = col >> 6, d = col & 63;
                    size_t o = ((size_t)(b * HDIM + h) * npos + pos) * DHD + d;
                    if (mode == 1) {
                        v0 = fast_sigmoid(v0); v1 = fast_sigmoid(v1);
                        *(float2*)&gb.outF[z][o] = make_float2(v0, v1);
                    } else {
                        __nv_bfloat16 h0 = __float2bfloat16(v0), h1 = __float2bfloat16(v1);
                        __nv_bfloat16 l0 = __float2bfloat16(v0 - __bfloat162float(h0));
                        __nv_bfloat16 l1 = __float2bfloat16(v1 - __bfloat162float(h1));
                        *(__nv_bfloat162*)&gb.outHi[z][o] = __nv_bfloat162(h0, h1);
                        *(__nv_bfloat162*)&gb.outLo[z][o] = __nv_bfloat162(l0, l1);
                    }
                }
            }
        }
    }
}

#define GM_SMEM_128 (3 * (2 * 128 * 64 + 2 * 128 * 64) + 64)
#define GM_SMEM_64  (3 * (2 * 64  * 64 + 2 * 128 * 64) + 64)

// ---------------- fused per-row stats (q + k in one launch) ----------------
__global__ void k_stats(const __nv_bfloat16* __restrict__ qhi, const __nv_bfloat16* __restrict__ qlo,
                        const __nv_bfloat16* __restrict__ k1hi, const __nv_bfloat16* __restrict__ k1lo,
                        const __nv_bfloat16* __restrict__ k2hi, const __nv_bfloat16* __restrict__ k2lo,
                        float* __restrict__ ll, float* __restrict__ vv,
                        float* __restrict__ aa, float* __restrict__ va)
{
    int gw = (blockIdx.x * blockDim.x + threadIdx.x) >> 5;
    int lane = threadIdx.x & 31;
    if (gw < BH*LQ) {
        const __nv_bfloat162* h = (const __nv_bfloat162*)(qhi + (size_t)gw * DHD);
        const __nv_bfloat162* l = (const __nv_bfloat162*)(qlo + (size_t)gw * DHD);
        __nv_bfloat162 hv = h[lane], lv = l[lane];
        float x0 = __bfloat162float(hv.x) + __bfloat162float(lv.x);
        float x1 = __bfloat162float(hv.y) + __bfloat162float(lv.y);
        float s = x0*x0 + x1*x1;
#pragma unroll
        for (int o = 16; o; o >>= 1) s += __shfl_xor_sync(0xffffffffu, s, o);
        if (!lane) ll[gw] = s;
    } else {
        int kw = gw - BH*LQ;
        if (kw >= BH*SK) return;
        const __nv_bfloat162* ah = (const __nv_bfloat162*)(k1hi + (size_t)kw * DHD);
        const __nv_bfloat162* al = (const __nv_bfloat162*)(k1lo + (size_t)kw * DHD);
        const __nv_bfloat162* bh = (const __nv_bfloat162*)(k2hi + (size_t)kw * DHD);
        const __nv_bfloat162* bl = (const __nv_bfloat162*)(k2lo + (size_t)kw * DHD);
        __nv_bfloat162 a2 = ah[lane], a2l = al[lane], b2 = bh[lane], b2l = bl[lane];
        float a0 = __bfloat162float(a2.x) + __bfloat162float(a2l.x);
        float a1 = __bfloat162float(a2.y) + __bfloat162float(a2l.y);
        float b0 = __bfloat162float(b2.x) + __bfloat162float(b2l.x);
        float b1 = __bfloat162float(b2.y) + __bfloat162float(b2l.y);
        float svv = a0*a0 + a1*a1, saa = b0*b0 + b1*b1, sva = a0*b0 + a1*b1;
#pragma unroll
        for (int o = 16; o; o >>= 1) {
            svv += __shfl_xor_sync(0xffffffffu, svv, o);
            saa += __shfl_xor_sync(0xffffffffu, saa, o);
            sva += __shfl_xor_sync(0xffffffffu, sva, o);
        }
        if (!lane) { vv[kw] = svv; aa[kw] = saa; va[kw] = sva; }
    }
}

// ================== logits via bf16x3 MMA + poly sqrt ==================
#define LG_PAD 72
#define LG_QT (64 * LG_PAD * 2)
#define LG_KT (128 * LG_PAD * 2)
#define LG_SMEM (2*LG_QT + 4*LG_KT)

__global__ void __launch_bounds__(256, 2)
k_logits_mma(const __nv_bfloat16* __restrict__ qhi, const __nv_bfloat16* __restrict__ qlo,
             const __nv_bfloat16* __restrict__ k1hi, const __nv_bfloat16* __restrict__ k1lo,
             const __nv_bfloat16* __restrict__ k2hi, const __nv_bfloat16* __restrict__ k2lo,
             const float* __restrict__ ll, const float* __restrict__ vv,
             const float* __restrict__ aa, const float* __restrict__ va,
             float* __restrict__ A)
{
    extern __shared__ char smem[];
    const uint32_t sb = smem_to_u32(smem);
    const int tid = threadIdx.x, wid = tid >> 5, lane = tid & 31;
    const int bh = blockIdx.z, l0 = blockIdx.y << 6, s0 = blockIdx.x << 7;
    const uint32_t oQh = 0, oQl = LG_QT, oK1h = 2*LG_QT, oK1l = 2*LG_QT + LG_KT,
                   oK2h = 2*LG_QT + 2*LG_KT, oK2l = 2*LG_QT + 3*LG_KT;

    {
        const __nv_bfloat16* qh = qhi + ((size_t)(bh * LQ + l0) << 6);
        const __nv_bfloat16* ql = qlo + ((size_t)(bh * LQ + l0) << 6);
#pragma unroll
        for (int i = tid; i < 512; i += 256) {
            int r = i >> 3, c = i & 7;
            uint32_t d = (uint32_t)(r * (LG_PAD*2) + c * 16);
            *(uint4*)(smem + oQh + d) = *(const uint4*)(qh + (r << 6) + (c << 3));
            *(uint4*)(smem + oQl + d) = *(const uint4*)(ql + (r << 6) + (c << 3));
        }
        const __nv_bfloat16* p1h = k1hi + ((size_t)(bh * SK + s0) << 6);
        const __nv_bfloat16* p1l = k1lo + ((size_t)(bh * SK + s0) << 6);
        const __nv_bfloat16* p2h = k2hi + ((size_t)(bh * SK + s0) << 6);
        const __nv_bfloat16* p2l = k2lo + ((size_t)(bh * SK + s0) << 6);
#pragma unroll
        for (int i = tid; i < 1024; i += 256) {
            int r = i >> 3, c = i & 7;
            uint32_t d = (uint32_t)(r * (LG_PAD*2) + c * 16);
            *(uint4*)(smem + oK1h + d) = *(const uint4*)(p1h + (r << 6) + (c << 3));
            *(uint4*)(smem + oK1l + d) = *(const uint4*)(p1l + (r << 6) + (c << 3));
            *(uint4*)(smem + oK2h + d) = *(const uint4*)(p2h + (r << 6) + (c << 3));
            *(uint4*)(smem + oK2l + d) = *(const uint4*)(p2l + (r << 6) + (c << 3));
        }
    }
    __syncthreads();

    const int wm = (wid & 1) << 5, wn = (wid >> 1) << 5;
    float lv[2][4][4] = {}, la[2][4][4] = {};
#pragma unroll
    for (int kk = 0; kk < 4; kk++) {
        const uint32_t coff = (uint32_t)(kk * 16 + ((lane >> 4) << 3)) * 2u;
        uint32_t af[2][4], alf[2][4];
#pragma unroll
        for (int mt = 0; mt < 2; mt++) {
            uint32_t ra = (uint32_t)((wm + mt * 16 + (lane & 15)) * LG_PAD) * 2u + coff;
            ldm_x4(af[mt],  sb + oQh + ra);
            ldm_x4(alf[mt], sb + oQl + ra);
        }
        uint32_t b1h[2][4], b1l[2][4], b2h[2][4], b2l[2][4];
#pragma unroll
        for (int ng = 0; ng < 2; ng++) {
            uint32_t rb = (uint32_t)((wn + ng * 16 + (lane & 15)) * LG_PAD) * 2u + coff;
            ldm_x4(b1h[ng], sb + oK1h + rb);
            ldm_x4(b1l[ng], sb + oK1l + rb);
            ldm_x4(b2h[ng], sb + oK2h + rb);
            ldm_x4(b2l[ng], sb + oK2l + rb);
        }
#pragma unroll
        for (int mt = 0; mt < 2; mt++)
#pragma unroll
            for (int nt = 0; nt < 4; nt++) {
                const int ng = nt >> 1, sel = nt & 1;
                mma16816(lv[mt][nt], af[mt],  b1h[ng][sel], b1h[ng][sel + 2]);
                mma16816(lv[mt][nt], af[mt],  b1l[ng][sel], b1l[ng][sel + 2]);
                mma16816(lv[mt][nt], alf[mt], b1h[ng][sel], b1h[ng][sel + 2]);
                mma16816(la[mt][nt], af[mt],  b2h[ng][sel], b2h[ng][sel + 2]);
                mma16816(la[mt][nt], af[mt],  b2l[ng][sel], b2l[ng][sel + 2]);
                mma16816(la[mt][nt], alf[mt], b2h[ng][sel], b2h[ng][sel + 2]);
            }
    }

    const int qr = lane >> 2, qc = (lane & 3) << 1;
    float vvc[8], aac[8], vac[8];
#pragma unroll
    for (int nt = 0; nt < 4; nt++)
#pragma unroll
        for (int j = 0; j < 2; j++) {
            int c = bh * SK + s0 + wn + nt * 8 + qc + j;
            vvc[nt*2+j] = __ldg(&vv[c]); aac[nt*2+j] = __ldg(&aa[c]); vac[nt*2+j] = __ldg(&va[c]);
        }
#pragma unroll
    for (int mt = 0; mt < 2; mt++)
#pragma unroll
        for (int half = 0; half < 2; half++) {
            int l = l0 + wm + mt * 16 + qr + (half << 3);
            float llr = __ldg(&ll[bh * LQ + l]);
            float* rowp = A + (((size_t)(bh * LQ + l)) << 10);
#pragma unroll
            for (int nt = 0; nt < 4; nt++) {
                float r2[2];
#pragma unroll
                for (int j = 0; j < 2; j++) {
                    float LV = lv[mt][nt][half * 2 + j];
                    float LA = la[mt][nt][half * 2 + j];
                    int ci = nt * 2 + j;
                    float det = llr * (vvc[ci] * aac[ci] - vac[ci] * vac[ci])
                              - LV * (LV * aac[ci] - LA * vac[ci])
                              + LA * (LV * vac[ci] - LA * vvc[ci]);
                    det = fmaxf(det, 1e-8f);
                    r2[j] = LV + LA - 1.5f * fast_sqrt(det);
                }
                *(float2*)&rowp[s0 + wn + nt * 8 + qc] = make_float2(r2[0], r2[1]);
            }
        }
}

// ---------------- fused softmax + head-average (R13 block-per-(b,l) version) ----------------
__global__ void k_softmax_avg(const float* __restrict__ A, __nv_bfloat16* __restrict__ Phi,
                              __nv_bfloat16* __restrict__ Plo, float* __restrict__ avg)
{
    const int bl = blockIdx.x;               // 0..2047
    const int b = bl >> 9, l = bl & (LQ - 1);
    const int t = threadIdx.x;
    __shared__ float sred[8];
    __shared__ float sinv;
    float pacc0 = 0.f, pacc1 = 0.f, pacc2 = 0.f, pacc3 = 0.f;

    for (int h = 0; h < HDIM; h++) {
        const size_t row = (size_t)(b * HDIM + h) * LQ + l;
        const float* p = A + (row << 10);
        float4 x = *(const float4*)(p + t * 4);
        float m = fmaxf(fmaxf(x.x, x.y), fmaxf(x.z, x.w));
#pragma unroll
        for (int o = 16; o; o >>= 1) m = fmaxf(m, __shfl_xor_sync(0xffffffffu, m, o));
        if ((t & 31) == 0) sred[t >> 5] = m;
        __syncthreads();
        if (t < 8) {
            float v = sred[t];
#pragma unroll
            for (int o = 4; o; o >>= 1) v = fmaxf(v, __shfl_xor_sync(0xffu, v, o));
            sred[t] = v;
        }
        __syncthreads();
        m = sred[0];
        float e0 = fast_exp(x.x - m), e1 = fast_exp(x.y - m);
        float e2 = fast_exp(x.z - m), e3 = fast_exp(x.w - m);
        float s = (e0 + e1) + (e2 + e3);
#pragma unroll
        for (int o = 16; o; o >>= 1) s += __shfl_xor_sync(0xffffffffu, s, o);
        if ((t & 31) == 0) sred[t >> 5] = s;
        __syncthreads();
        if (t < 8) {
            float v = sred[t];
#pragma unroll
            for (int o = 4; o; o >>= 1) v += __shfl_xor_sync(0xffu, v, o);
            if (t == 0) sinv = 1.0f / v;
        }
        __syncthreads();
        float inv = sinv;
        float v0 = e0 * inv, v1 = e1 * inv, v2 = e2 * inv, v3 = e3 * inv;
        pacc0 += v0; pacc1 += v1; pacc2 += v2; pacc3 += v3;
        __nv_bfloat16 h0 = __float2bfloat16(v0), h1 = __float2bfloat16(v1);
        __nv_bfloat16 h2 = __float2bfloat16(v2), h3 = __float2bfloat16(v3);
        __nv_bfloat16 l0 = __float2bfloat16(v0 - __bfloat162float(h0));
        __nv_bfloat16 l1 = __float2bfloat16(v1 - __bfloat162float(h1));
        __nv_bfloat16 l2 = __float2bfloat16(v2 - __bfloat162float(h2));
        __nv_bfloat16 l3 = __float2bfloat16(v3 - __bfloat162float(h3));
        size_t o = (row << 10) + t * 4;
        ((__nv_bfloat162*)(Phi + o))[0] = __nv_bfloat162(h0, h1);
        ((__nv_bfloat162*)(Phi + o))[1] = __nv_bfloat162(h2, h3);
        ((__nv_bfloat162*)(Plo + o))[0] = __nv_bfloat162(l0, l1);
        ((__nv_bfloat162*)(Plo + o))[1] = __nv_bfloat162(l2, l3);
        __syncthreads();
    }
    if (avg) {
        float4 a4 = make_float4(pacc0 * (1.f / HDIM), pacc1 * (1.f / HDIM),
                                pacc2 * (1.f / HDIM), pacc3 * (1.f / HDIM));
        *(float4*)&avg[(((size_t)b * LQ + l) << 10) + t * 4] = a4;
    }
}

// ================== attn @ V + gate + split -> cb ==================
#define AV_PAD 72
#define AV_T (64 * AV_PAD * 2)
#define AV_STAGE (6 * AV_T)
#define AV_SMEM (2 * AV_STAGE)

__global__ void __launch_bounds__(256, 2)
k_av_mma(const __nv_bfloat16* __restrict__ athi, const __nv_bfloat16* __restrict__ atlo,
         const __nv_bfloat16* __restrict__ v1hi, const __nv_bfloat16* __restrict__ v1lo,
         const __nv_bfloat16* __restrict__ v2hi, const __nv_bfloat16* __restrict__ v2lo,
         const float* __restrict__ G1, const float* __restrict__ G2,
         __nv_bfloat16* __restrict__ cbhi, __nv_bfloat16* __restrict__ cblo)
{
    extern __shared__ char smem[];
    const uint32_t sb = smem_to_u32(smem);
    const int tid = threadIdx.x, wid = tid >> 5, lane = tid & 31;
    const int bh = blockIdx.y, l0 = blockIdx.x << 6;
    const int wm = (wid & 1) << 5, wn = (wid >> 1) << 4;

    float acc1[2][2][4] = {}, acc2[2][2][4] = {};

#define AV_LOAD(stg, s0k) do { \
    _Pragma("unroll") \
    for (int i = 0; i < 12; i++) { \
        int id = (i << 8) + tid; \
        int a = id >> 9; \
        int rr = (id >> 3) & 63; \
        int c = id & 7; \
        const __nv_bfloat16* g; \
        if (a < 2) g = (a ? atlo : athi) + (((size_t)(bh * LQ + l0 + rr)) << 10) + (s0k) + (c << 3); \
        else { \
            const __nv_bfloat16* vb = (a == 2) ? v1hi : (a == 3) ? v1lo : (a == 4) ? v2hi : v2lo; \
            g = vb + (((size_t)(bh * SK + (s0k) + rr)) << 6) + (c << 3); \
        } \
        uint32_t sa = sb + (uint32_t)(stg) * AV_STAGE + (uint32_t)a * AV_T + (uint32_t)(rr * (AV_PAD*2) + c * 16); \
        CP_ASYNC16(sa, g); \
    } \
    CP_COMMIT(); \
} while (0)

    AV_LOAD(0, 0);

    for (int ch = 0; ch < 16; ch++) {
        const int stg = ch & 1;
        if (ch + 1 < 16) { AV_LOAD(stg ^ 1, (ch + 1) << 6); CP_WAIT(1); }
        else             { CP_WAIT(0); }
        __syncthreads();

        const uint32_t st = sb + (uint32_t)stg * AV_STAGE;
#pragma unroll
        for (int kk = 0; kk < 4; kk++) {
            const uint32_t coff = (uint32_t)(kk * 16 + ((lane >> 4) << 3)) * 2u;
            uint32_t af[2][4], alf[2][4];
#pragma unroll
            for (int mt = 0; mt < 2; mt++) {
                uint32_t ra = (uint32_t)((wm + mt * 16 + (lane & 15)) * AV_PAD) * 2u + coff;
                ldm_x4(af[mt],  st + ra);
                ldm_x4(alf[mt], st + AV_T + ra);
            }
            uint32_t bv1h[4], bv1l[4], bv2h[4], bv2l[4];
            {
                uint32_t rb = (uint32_t)((kk * 16 + (lane & 15)) * AV_PAD + wn + ((lane >> 4) << 3)) * 2u;
                ldm_x4_t(bv1h, st + 2 * AV_T + rb);
                ldm_x4_t(bv1l, st + 3 * AV_T + rb);
                ldm_x4_t(bv2h, st + 4 * AV_T + rb);
                ldm_x4_t(bv2l, st + 5 * AV_T + rb);
            }
#pragma unroll
            for (int mt = 0; mt < 2; mt++)
#pragma unroll
                for (int nt = 0; nt < 2; nt++) {
                    mma16816(acc1[mt][nt], af[mt],  bv1h[nt*2], bv1h[nt*2+1]);
                    mma16816(acc1[mt][nt], af[mt],  bv1l[nt*2], bv1l[nt*2+1]);
                    mma16816(acc1[mt][nt], alf[mt], bv1h[nt*2], bv1h[nt*2+1]);
                    mma16816(acc2[mt][nt], af[mt],  bv2h[nt*2], bv2h[nt*2+1]);
                    mma16816(acc2[mt][nt], af[mt],  bv2l[nt*2], bv2l[nt*2+1]);
                    mma16816(acc2[mt][nt], alf[mt], bv2h[nt*2], bv2h[nt*2+1]);
                }
        }
        __syncthreads();
    }

    const int qr = lane >> 2, qc = (lane & 3) << 1;
    const int b_ = bh >> 4, h_ = bh & 15;
#pragma unroll
    for (int mt = 0; mt < 2; mt++)
#pragma unroll
        for (int half = 0; half < 2; half++) {
            int l = l0 + wm + mt * 16 + qr + (half << 3);
            const float* g1r = G1 + ((size_t)(bh * LQ + l)) * DHD;
            const float* g2r = G2 + ((size_t)(bh * LQ + l)) * DHD;
            size_t rowo = ((size_t)(l * BDIM + b_)) << 10;
#pragma unroll
            for (int nt = 0; nt < 2; nt++) {
                int d = wn + nt * 8 + qc;
                float2 g1 = *(const float2*)&g1r[d];
                float2 g2 = *(const float2*)&g2r[d];
                float c0 = (acc1[mt][nt][half*2+0] * g1.x + acc2[mt][nt][half*2+0] * g2.x) * 0.5f;
                float c1 = (acc1[mt][nt][half*2+1] * g1.y + acc2[mt][nt][half*2+1] * g2.y) * 0.5f;
                __nv_bfloat16 h0 = __float2bfloat16(c0), h1 = __float2bfloat16(c1);
                __nv_bfloat16 l0b = __float2bfloat16(c0 - __bfloat162float(h0));
                __nv_bfloat16 l1b = __float2bfloat16(c1 - __bfloat162float(h1));
                size_t o = rowo + h_ * DHD + d;
                *(__nv_bfloat162*)&cbhi[o] = __nv_bfloat162(h0, h1);
                *(__nv_bfloat162*)&cblo[o] = __nv_bfloat162(l0b, l1b);
            }
        }
#undef AV_LOAD
}

// ---------------- launch ----------------
extern "C" void kernel_launch(void* const* d_in, const int* in_sizes, int n_in,
                              void* d_out, int out_size)
{
    const float* query = (const float*)d_in[0];
    const float* mod1  = (const float*)d_in[1];
    const float* mod2  = (const float*)d_in[2];
    WPtrs wp;
    const float* bi[8];
    for (int i = 0; i < 8; i++) {
        wp.p[i] = (const float*)d_in[3 + 2*i];
        bi[i]   = (const float*)d_in[4 + 2*i];
    }
    float* out = (float*)d_out;
    float* avg_out = ((size_t)out_size >= 2ULL * LQ * BDIM * EDIM)
                   ? out + (size_t)LQ * BDIM * EDIM : nullptr;

    float *G1h, *G2h, *ll, *vv, *aa, *va, *Attn;
    cudaGetSymbolAddress((void**)&G1h, g_G1h);
    cudaGetSymbolAddress((void**)&G2h, g_G2h);
    cudaGetSymbolAddress((void**)&ll,  g_ll);
    cudaGetSymbolAddress((void**)&vv,  g_vv);
    cudaGetSymbolAddress((void**)&aa,  g_aa);
    cudaGetSymbolAddress((void**)&va,  g_va);
    cudaGetSymbolAddress((void**)&Attn, g_Attn);

    __nv_bfloat16 *qhi,*qlo,*k1hi,*k1lo,*k2hi,*k2lo,*v1hi,*v1lo,*v2hi,*v2lo,*athi,*atlo;
    __nv_bfloat16 *xq_hi,*xq_lo,*m1_hi,*m1_lo,*m2_hi,*m2_lo,*cb_hi,*cb_lo,*wt_hi,*wt_lo;
    cudaGetSymbolAddress((void**)&qhi,  g_q_hi);  cudaGetSymbolAddress((void**)&qlo,  g_q_lo);
    cudaGetSymbolAddress((void**)&k1hi, g_k1_hi); cudaGetSymbolAddress((void**)&k1lo, g_k1_lo);
    cudaGetSymbolAddress((void**)&k2hi, g_k2_hi); cudaGetSymbolAddress((void**)&k2lo, g_k2_lo);
    cudaGetSymbolAddress((void**)&v1hi, g_v1_hi); cudaGetSymbolAddress((void**)&v1lo, g_v1_lo);
    cudaGetSymbolAddress((void**)&v2hi, g_v2_hi); cudaGetSymbolAddress((void**)&v2lo, g_v2_lo);
    cudaGetSymbolAddress((void**)&athi, g_at_hi); cudaGetSymbolAddress((void**)&atlo, g_at_lo);
    cudaGetSymbolAddress((void**)&xq_hi, g_xq_hi); cudaGetSymbolAddress((void**)&xq_lo, g_xq_lo);
    cudaGetSymbolAddress((void**)&m1_hi, g_m1_hi); cudaGetSymbolAddress((void**)&m1_lo, g_m1_lo);
    cudaGetSymbolAddress((void**)&m2_hi, g_m2_hi); cudaGetSymbolAddress((void**)&m2_lo, g_m2_lo);
    cudaGetSymbolAddress((void**)&cb_hi, g_cb_hi); cudaGetSymbolAddress((void**)&cb_lo, g_cb_lo);
    cudaGetSymbolAddress((void**)&wt_hi, g_wt_hi); cudaGetSymbolAddress((void**)&wt_lo, g_wt_lo);

    cudaFuncSetAttribute(gemm_mma<128>, cudaFuncAttributeMaxDynamicSharedMemorySize, GM_SMEM_128);
    cudaFuncSetAttribute(gemm_mma<64>,  cudaFuncAttributeMaxDynamicSharedMemorySize, GM_SMEM_64);
    cudaFuncSetAttribute(k_logits_mma,  cudaFuncAttributeMaxDynamicSharedMemorySize, LG_SMEM);
    cudaFuncSetAttribute(k_av_mma,      cudaFuncAttributeMaxDynamicSharedMemorySize, AV_SMEM);

    // merged preprocessing: input split (blocks 0..10239) + weight transpose/split (10240..18431)
    k_prep<<<18432, 256>>>(query, mod1, mod2, wp,
                           xq_hi, xq_lo, m1_hi, m1_lo, m2_hi, m2_lo, wt_hi, wt_lo);

    size_t WSZ = (size_t)1024*1024;

    // ---- ALL 7 projections in ONE TM=128 launch ----
    {
        GemmBatch gb = {};
        const __nv_bfloat16* As[4]  = {m1_hi, m2_hi, m1_hi, m2_hi};
        const __nv_bfloat16* Als[4] = {m1_lo, m2_lo, m1_lo, m2_lo};
        __nv_bfloat16* oh[4] = {k1hi, k2hi, v1hi, v2hi};
        __nv_bfloat16* ol[4] = {k1lo, k2lo, v1lo, v2lo};
        for (int z = 0; z < 4; z++) {
            gb.Ahi[z] = As[z]; gb.Alo[z] = Als[z];
            gb.Bhi[z] = wt_hi + (size_t)(1 + z) * WSZ;
            gb.Blo[z] = wt_lo + (size_t)(1 + z) * WSZ;
            gb.bias[z] = bi[1 + z];
            gb.outHi[z] = oh[z]; gb.outLo[z] = ol[z];
            gb.outF[z] = nullptr;
            gb.scale[z] = 1.f; gb.mode[z] = 0; gb.rows[z] = 4096; gb.npos[z] = SK;
        }
        gb.Ahi[4] = gb.Ahi[5] = gb.Ahi[6] = xq_hi;
        gb.Alo[4] = gb.Alo[5] = gb.Alo[6] = xq_lo;
        gb.Bhi[4] = wt_hi + 0*WSZ; gb.Blo[4] = wt_lo + 0*WSZ; gb.bias[4] = bi[0];
        gb.Bhi[5] = wt_hi + 5*WSZ; gb.Blo[5] = wt_lo + 5*WSZ; gb.bias[5] = bi[5];
        gb.Bhi[6] = wt_hi + 6*WSZ; gb.Blo[6] = wt_lo + 6*WSZ; gb.bias[6] = bi[6];
        gb.outHi[4] = qhi; gb.outLo[4] = qlo; gb.outF[4] = nullptr;
        gb.scale[4] = 0.125f; gb.mode[4] = 0; gb.rows[4] = 2048; gb.npos[4] = LQ;
        gb.outF[5] = G1h; gb.scale[5] = 1.f; gb.mode[5] = 1; gb.rows[5] = 2048; gb.npos[5] = LQ;
        gb.outF[6] = G2h; gb.scale[6] = 1.f; gb.mode[6] = 1; gb.rows[6] = 2048; gb.npos[6] = LQ;
        gemm_mma<128><<<dim3(8, 32, 7), 256, GM_SMEM_128>>>(gb);
    }

    // fused stats (q + k1/k2 in one launch)
    k_stats<<<((BH*LQ + BH*SK) * 32 + 255) / 256, 256>>>(
        qhi, qlo, k1hi, k1lo, k2hi, k2lo, ll, vv, aa, va);

    k_logits_mma<<<dim3(SK/128, LQ/64, BH), 256, LG_SMEM>>>(
        qhi, qlo, k1hi, k1lo, k2hi, k2lo, ll, vv, aa, va, Attn);

    k_softmax_avg<<<BDIM*LQ, 256>>>(Attn, athi, atlo, avg_out);

    k_av_mma<<<dim3(LQ/64, BH), 256, AV_SMEM>>>(athi, atlo, v1hi, v1lo, v2hi, v2lo,
                                                G1h, G2h, cb_hi, cb_lo);

    // ---- output projection ----
    {
        GemmBatch gb = {};
        gb.Ahi[0] = cb_hi; gb.Alo[0] = cb_lo;
        gb.Bhi[0] = wt_hi + 7*WSZ; gb.Blo[0] = wt_lo + 7*WSZ; gb.bias[0] = bi[7];
        gb.outF[0] = out; gb.scale[0] = 1.f; gb.mode[0] = 2;
        gb.rows[0] = 2048; gb.npos[0] = LQ;
        gemm_mma<64><<<dim3(8, 32, 1), 256, GM_SMEM_64>>>(gb);
    }
}

// round 17
// speedup vs baseline: 1.0248x; 1.0248x over previous
#include <cuda_runtime.h>
#include <cuda_bf16.h>
#include <math.h>
#include <stdint.h>

#define EDIM 1024
#define BDIM 4
#define HDIM 16
#define DHD 64
#define LQ 512
#define SK 1024
#define BH 64   // BDIM*HDIM

// ======================= helpers =======================
__device__ __forceinline__ uint32_t smem_to_u32(const void* smem_ptr) {
    uint32_t addr;
    asm("{ .reg .u64 tmp; cvta.to.shared.u64 tmp, %1; cvt.u32.u64 %0, tmp; }"
        : "=r"(addr) : "l"(smem_ptr));
    return addr;
}
__device__ __forceinline__ void ldm_x4(uint32_t* r, uint32_t addr) {
    asm volatile("ldmatrix.sync.aligned.m8n8.x4.shared.b16 {%0,%1,%2,%3}, [%4];"
        : "=r"(r[0]), "=r"(r[1]), "=r"(r[2]), "=r"(r[3]) : "r"(addr));
}
__device__ __forceinline__ void ldm_x4_t(uint32_t* r, uint32_t addr) {
    asm volatile("ldmatrix.sync.aligned.m8n8.x4.trans.shared.b16 {%0,%1,%2,%3}, [%4];"
        : "=r"(r[0]), "=r"(r[1]), "=r"(r[2]), "=r"(r[3]) : "r"(addr));
}
__device__ __forceinline__ void mma16816(float* d, const uint32_t* a, uint32_t b0, uint32_t b1) {
    asm volatile("mma.sync.aligned.m16n8k16.row.col.f32.bf16.bf16.f32 "
        "{%0,%1,%2,%3}, {%4,%5,%6,%7}, {%8,%9}, {%0,%1,%2,%3};"
        : "+f"(d[0]), "+f"(d[1]), "+f"(d[2]), "+f"(d[3])
        : "r"(a[0]), "r"(a[1]), "r"(a[2]), "r"(a[3]), "r"(b0), "r"(b1));
}
#define CP_ASYNC16(saddr, gptr) \
    asm volatile("cp.async.cg.shared.global [%0], [%1], 16;" :: "r"(saddr), "l"(gptr))
#define CP_COMMIT()  asm volatile("cp.async.commit_group;" ::: "memory")
#define CP_WAIT(N)   asm volatile("cp.async.wait_group %0;" :: "n"(N) : "memory")

// ---- MUFU-free math ----
__device__ __forceinline__ float fast_sqrt(float x) {
    float r = __int_as_float(0x5f3759df - (__float_as_int(x) >> 1));
    r = r * fmaf(-0.5f * x * r, r, 1.5f);
    r = r * fmaf(-0.5f * x * r, r, 1.5f);
    r = r * fmaf(-0.5f * x * r, r, 1.5f);
    return x * r;
}
__device__ __forceinline__ float fast_exp(float x) {
    float y = x * 1.44269504f;
    y = fmaxf(fminf(y, 126.0f), -125.0f);
    float t = y + 12582912.f;
    int n = __float_as_int(t) - 0x4B400000;
    float f = y - (t - 12582912.f);
    float p = 1.33335581e-3f;
    p = fmaf(p, f, 9.61812910e-3f);
    p = fmaf(p, f, 5.55041086e-2f);
    p = fmaf(p, f, 2.40226507e-1f);
    p = fmaf(p, f, 6.93147181e-1f);
    p = fmaf(p, f, 1.0f);
    return __int_as_float(__float_as_int(p) + (n << 23));
}
__device__ __forceinline__ float fast_rcp(float x) {
    float r = __int_as_float(0x7EF311C3 - __float_as_int(x));
    r = r * (2.0f - x * r);
    r = r * (2.0f - x * r);
    r = r * (2.0f - x * r);
    return r;
}
__device__ __forceinline__ float fast_sigmoid(float x) {
    return fast_rcp(1.0f + fast_exp(-x));
}

// ---------------- scratch ----------------
__device__ float g_G1h[BH*LQ*DHD];
__device__ float g_G2h[BH*LQ*DHD];
__device__ float g_ll [BH*LQ];
__device__ float g_vv [BH*SK];
__device__ float g_aa [BH*SK];
__device__ float g_va [BH*SK];
__device__ float g_Attn[BH*LQ*SK];

__device__ __align__(16) __nv_bfloat16 g_q_hi [BH*LQ*DHD];
__device__ __align__(16) __nv_bfloat16 g_q_lo [BH*LQ*DHD];
__device__ __align__(16) __nv_bfloat16 g_k1_hi[BH*SK*DHD];
__device__ __align__(16) __nv_bfloat16 g_k1_lo[BH*SK*DHD];
__device__ __align__(16) __nv_bfloat16 g_k2_hi[BH*SK*DHD];
__device__ __align__(16) __nv_bfloat16 g_k2_lo[BH*SK*DHD];
__device__ __align__(16) __nv_bfloat16 g_v1_hi[BH*SK*DHD];
__device__ __align__(16) __nv_bfloat16 g_v1_lo[BH*SK*DHD];
__device__ __align__(16) __nv_bfloat16 g_v2_hi[BH*SK*DHD];
__device__ __align__(16) __nv_bfloat16 g_v2_lo[BH*SK*DHD];
__device__ __align__(16) __nv_bfloat16 g_at_hi[BH*LQ*SK];
__device__ __align__(16) __nv_bfloat16 g_at_lo[BH*LQ*SK];
__device__ __align__(16) __nv_bfloat16 g_xq_hi[2048*1024];
__device__ __align__(16) __nv_bfloat16 g_xq_lo[2048*1024];
__device__ __align__(16) __nv_bfloat16 g_m1_hi[4096*1024];
__device__ __align__(16) __nv_bfloat16 g_m1_lo[4096*1024];
__device__ __align__(16) __nv_bfloat16 g_m2_hi[4096*1024];
__device__ __align__(16) __nv_bfloat16 g_m2_lo[4096*1024];
__device__ __align__(16) __nv_bfloat16 g_cb_hi[2048*1024];
__device__ __align__(16) __nv_bfloat16 g_cb_lo[2048*1024];
__device__ __align__(16) __nv_bfloat16 g_wt_hi[8*1024*1024];
__device__ __align__(16) __nv_bfloat16 g_wt_lo[8*1024*1024];

// ---------------- fused input split ----------------
__global__ void k_split_all(const float* __restrict__ q, const float* __restrict__ m1,
                            const float* __restrict__ m2,
                            __nv_bfloat16* __restrict__ qhi, __nv_bfloat16* __restrict__ qlo,
                            __nv_bfloat16* __restrict__ m1hi, __nv_bfloat16* __restrict__ m1lo,
                            __nv_bfloat16* __restrict__ m2hi, __nv_bfloat16* __restrict__ m2lo)
{
    int i = blockIdx.x * 256 + threadIdx.x;
    const float* src; __nv_bfloat16 *hi, *lo; int off;
    if (i < 512*1024)        { src = q;  hi = qhi;  lo = qlo;  off = i; }
    else if (i < 1536*1024)  { src = m1; hi = m1hi; lo = m1lo; off = i - 512*1024; }
    else                     { src = m2; hi = m2hi; lo = m2lo; off = i - 1536*1024; }
    float4 v = ((const float4*)src)[off];
    __nv_bfloat16 h0 = __float2bfloat16(v.x), h1 = __float2bfloat16(v.y);
    __nv_bfloat16 h2 = __float2bfloat16(v.z), h3 = __float2bfloat16(v.w);
    __nv_bfloat16 l0 = __float2bfloat16(v.x - __bfloat162float(h0));
    __nv_bfloat16 l1 = __float2bfloat16(v.y - __bfloat162float(h1));
    __nv_bfloat16 l2 = __float2bfloat16(v.z - __bfloat162float(h2));
    __nv_bfloat16 l3 = __float2bfloat16(v.w - __bfloat162float(h3));
    __nv_bfloat162* hp = (__nv_bfloat162*)(hi + (size_t)off * 4);
    __nv_bfloat162* lp = (__nv_bfloat162*)(lo + (size_t)off * 4);
    hp[0] = __nv_bfloat162(h0, h1); hp[1] = __nv_bfloat162(h2, h3);
    lp[0] = __nv_bfloat162(l0, l1); lp[1] = __nv_bfloat162(l2, l3);
}

// ---------------- weight transpose + split ----------------
struct WPtrs { const float* p[8]; };
__global__ void k_wsplit_all(WPtrs wp, __nv_bfloat16* __restrict__ ThiAll,
                             __nv_bfloat16* __restrict__ TloAll)
{
    __shared__ float t[32][33];
    const int wi = blockIdx.z;
    const float* W = wp.p[wi];
    __nv_bfloat16* Thi = ThiAll + (size_t)wi * 1024 * 1024;
    __nv_bfloat16* Tlo = TloAll + (size_t)wi * 1024 * 1024;
    const int bx = blockIdx.x << 5;
    const int by = blockIdx.y << 5;
    const int x = threadIdx.x, y = threadIdx.y;
#pragma unroll
    for (int i = 0; i < 32; i += 8)
        t[y + i][x] = W[(size_t)(by + y + i) * EDIM + bx + x];
    __syncthreads();
#pragma unroll
    for (int i = 0; i < 32; i += 8) {
        float v = t[x][y + i];
        __nv_bfloat16 h = __float2bfloat16(v);
        __nv_bfloat16 l = __float2bfloat16(v - __bfloat162float(h));
        size_t o = (size_t)(bx + y + i) * EDIM + by + x;
        Thi[o] = h; Tlo[o] = l;
    }
}

// ================== batched warp-MMA bf16x3 GEMM (up to 8 z-slices) ==================
struct GemmBatch {
    const __nv_bfloat16* Ahi[8];
    const __nv_bfloat16* Alo[8];
    const __nv_bfloat16* Bhi[8];
    const __nv_bfloat16* Blo[8];
    const float* bias[8];
    float* outF[8];
    __nv_bfloat16* outHi[8];
    __nv_bfloat16* outLo[8];
    float scale[8];
    int   mode[8];
    int   rows[8];
    int   npos[8];
};

template <int TM>
__global__ void __launch_bounds__(256, (TM == 64 ? 3 : 2))
gemm_mma(GemmBatch gb)
{
    constexpr int ATILE = TM * 64;
    constexpr int BTILE = 128 * 64;
    constexpr int STAGE = 2 * ATILE + 2 * BTILE;
    constexpr int MW = TM / 32;
    constexpr int WN = 128 / (8 / MW);
    constexpr int NT = WN / 8;
    constexpr int ACH = TM * 4;
    constexpr int CH = (2 * ACH + 1024) / 256;
    constexpr int NITER = 32;

    const int z = blockIdx.z;
    const int m0 = blockIdx.y * TM, n0 = blockIdx.x << 7;
    if (m0 >= gb.rows[z]) return;
    const float* __restrict__ bias = gb.bias[z];
    const float scale = gb.scale[z];
    const int mode = gb.mode[z];
    const int npos = gb.npos[z];

    extern __shared__ char smem[];
    const uint32_t sb = (smem_to_u32(smem) + 63u) & ~63u;
    const int tid = threadIdx.x;
    const int wid = tid >> 5, lane = tid & 31;
    const int wm = (wid % MW) << 5;
    const int wn = (wid / MW) * WN;

    float acc[2][NT][4];
#pragma unroll
    for (int i = 0; i < 2; i++)
#pragma unroll
        for (int j = 0; j < NT; j++)
#pragma unroll
            for (int q = 0; q < 4; q++) acc[i][j][q] = 0.f;

    const __nv_bfloat16* gptr[CH];
    uint32_t soff[CH];
#pragma unroll
    for (int i = 0; i < CH; i++) {
        int cid = (i << 8) + tid;
        const __nv_bfloat16* gp; int rowbase; uint32_t toff; int local;
        if (cid < ACH)               { gp = gb.Ahi[z]; rowbase = m0; toff = 0;                 local = cid; }
        else if (cid < 2 * ACH)      { gp = gb.Alo[z]; rowbase = m0; toff = ATILE;             local = cid - ACH; }
        else if (cid < 2 * ACH + 512){ gp = gb.Bhi[z]; rowbase = n0; toff = 2 * ATILE;         local = cid - 2 * ACH; }
        else                         { gp = gb.Blo[z]; rowbase = n0; toff = 2 * ATILE + BTILE; local = cid - 2 * ACH - 512; }
        int r = local >> 2, c = local & 3;
        gptr[i] = gp + (((size_t)(rowbase + r)) << 10) + (c << 3);
        soff[i] = toff + (uint32_t)(r << 6) + (uint32_t)((c ^ ((r >> 1) & 3)) << 4);
    }
    auto load_stage = [&](int s) {
        uint32_t base = sb + (uint32_t)s * STAGE;
#pragma unroll
        for (int i = 0; i < CH; i++) {
            CP_ASYNC16(base + soff[i], gptr[i]);
            gptr[i] += 32;
        }
        CP_COMMIT();
    };

    load_stage(0);
    load_stage(1);

    uint32_t lA[2], lB[NT / 2];
#pragma unroll
    for (int mt = 0; mt < 2; mt++) {
        int r = wm + mt * 16 + (lane & 15);
        lA[mt] = (uint32_t)(r << 6) + (uint32_t)((((lane >> 4) ^ ((r >> 1) & 3))) << 4);
    }
#pragma unroll
    for (int ng = 0; ng < NT / 2; ng++) {
        int r = wn + ng * 16 + (lane & 15);
        lB[ng] = 2u * ATILE + (uint32_t)(r << 6) + (uint32_t)((((lane >> 4) ^ ((r >> 1) & 3))) << 4);
    }

    for (int it = 0; it < NITER; it++) {
        const int s = it % 3;
        CP_WAIT(1);
        __syncthreads();
        if (it + 2 < NITER) load_stage((it + 2) % 3);
        else CP_COMMIT();

        const uint32_t st = sb + (uint32_t)s * STAGE;
#pragma unroll
        for (int kk = 0; kk < 2; kk++) {
            const uint32_t xv = (uint32_t)(kk << 5);
            uint32_t ahi[2][4], alo[2][4];
#pragma unroll
            for (int mt = 0; mt < 2; mt++) {
                uint32_t a = (st + lA[mt]) ^ xv;
                ldm_x4(ahi[mt], a);
                ldm_x4(alo[mt], a + ATILE);
            }
#pragma unroll
            for (int ng = 0; ng < NT / 2; ng++) {
                uint32_t bhi[4], blo[4];
                uint32_t b = (st + lB[ng]) ^ xv;
                ldm_x4(bhi, b);
                ldm_x4(blo, b + BTILE);
#pragma unroll
                for (int mt = 0; mt < 2; mt++)
#pragma unroll
                    for (int sel = 0; sel < 2; sel++) {
                        const int nt = ng * 2 + sel;
                        mma16816(acc[mt][nt], ahi[mt], bhi[sel], bhi[sel + 2]);
                        mma16816(acc[mt][nt], ahi[mt], blo[sel], blo[sel + 2]);
                        mma16816(acc[mt][nt], alo[mt], bhi[sel], bhi[sel + 2]);
                    }
            }
        }
    }
    CP_WAIT(0);

    // ---- epilogue ----
    const int qr = lane >> 2, qc = (lane & 3) << 1;
#pragma unroll
    for (int mt = 0; mt < 2; mt++) {
#pragma unroll
        for (int nt = 0; nt < NT; nt++) {
#pragma unroll
            for (int half = 0; half < 2; half++) {
                int row = m0 + wm + mt * 16 + qr + (half << 3);
                int col = n0 + wn + nt * 8 + qc;
                float v0 = (acc[mt][nt][half * 2 + 0] + bias[col])     * scale;
                float v1 = (acc[mt][nt][half * 2 + 1] + bias[col + 1]) * scale;
                if (mode == 2) {
                    *(float2*)&gb.outF[z][(size_t)row * EDIM + col] = make_float2(v0, v1);
                } else {
                    int pos = row >> 2;              // B = 4
                    int b = row & 3;
                    int h = col >> 6, d = col & 63;
                    size_t o = ((size_t)(b * HDIM + h) * npos + pos) * DHD + d;
                    if (mode == 1) {
                        v0 = fast_sigmoid(v0); v1 = fast_sigmoid(v1);
                        *(float2*)&gb.outF[z][o] = make_float2(v0, v1);
                    } else {
                        __nv_bfloat16 h0 = __float2bfloat16(v0), h1 = __float2bfloat16(v1);
                        __nv_bfloat16 l0 = __float2bfloat16(v0 - __bfloat162float(h0));
                        __nv_bfloat16 l1 = __float2bfloat16(v1 - __bfloat162float(h1));
                        *(__nv_bfloat162*)&gb.outHi[z][o] = __nv_bfloat162(h0, h1);
                        *(__nv_bfloat162*)&gb.outLo[z][o] = __nv_bfloat162(l0, l1);
                    }
                }
            }
        }
    }
}

#define GM_SMEM_128 (3 * (2 * 128 * 64 + 2 * 128 * 64) + 64)
#define GM_SMEM_64  (3 * (2 * 64  * 64 + 2 * 128 * 64) + 64)

// ---------------- fused per-row stats (q + k in one launch) ----------------
__global__ void k_stats(const __nv_bfloat16* __restrict__ qhi, const __nv_bfloat16* __restrict__ qlo,
                        const __nv_bfloat16* __restrict__ k1hi, const __nv_bfloat16* __restrict__ k1lo,
                        const __nv_bfloat16* __restrict__ k2hi, const __nv_bfloat16* __restrict__ k2lo,
                        float* __restrict__ ll, float* __restrict__ vv,
                        float* __restrict__ aa, float* __restrict__ va)
{
    int gw = (blockIdx.x * blockDim.x + threadIdx.x) >> 5;
    int lane = threadIdx.x & 31;
    if (gw < BH*LQ) {
        const __nv_bfloat162* h = (const __nv_bfloat162*)(qhi + (size_t)gw * DHD);
        const __nv_bfloat162* l = (const __nv_bfloat162*)(qlo + (size_t)gw * DHD);
        __nv_bfloat162 hv = h[lane], lv = l[lane];
        float x0 = __bfloat162float(hv.x) + __bfloat162float(lv.x);
        float x1 = __bfloat162float(hv.y) + __bfloat162float(lv.y);
        float s = x0*x0 + x1*x1;
#pragma unroll
        for (int o = 16; o; o >>= 1) s += __shfl_xor_sync(0xffffffffu, s, o);
        if (!lane) ll[gw] = s;
    } else {
        int kw = gw - BH*LQ;
        if (kw >= BH*SK) return;
        const __nv_bfloat162* ah = (const __nv_bfloat162*)(k1hi + (size_t)kw * DHD);
        const __nv_bfloat162* al = (const __nv_bfloat162*)(k1lo + (size_t)kw * DHD);
        const __nv_bfloat162* bh = (const __nv_bfloat162*)(k2hi + (size_t)kw * DHD);
        const __nv_bfloat162* bl = (const __nv_bfloat162*)(k2lo + (size_t)kw * DHD);
        __nv_bfloat162 a2 = ah[lane], a2l = al[lane], b2 = bh[lane], b2l = bl[lane];
        float a0 = __bfloat162float(a2.x) + __bfloat162float(a2l.x);
        float a1 = __bfloat162float(a2.y) + __bfloat162float(a2l.y);
        float b0 = __bfloat162float(b2.x) + __bfloat162float(b2l.x);
        float b1 = __bfloat162float(b2.y) + __bfloat162float(b2l.y);
        float svv = a0*a0 + a1*a1, saa = b0*b0 + b1*b1, sva = a0*b0 + a1*b1;
#pragma unroll
        for (int o = 16; o; o >>= 1) {
            svv += __shfl_xor_sync(0xffffffffu, svv, o);
            saa += __shfl_xor_sync(0xffffffffu, saa, o);
            sva += __shfl_xor_sync(0xffffffffu, sva, o);
        }
        if (!lane) { vv[kw] = svv; aa[kw] = saa; va[kw] = sva; }
    }
}

// ================== logits via bf16x3 MMA + poly sqrt ==================
#define LG_PAD 72
#define LG_QT (64 * LG_PAD * 2)
#define LG_KT (128 * LG_PAD * 2)
#define LG_SMEM (2*LG_QT + 4*LG_KT)

__global__ void __launch_bounds__(256, 2)
k_logits_mma(const __nv_bfloat16* __restrict__ qhi, const __nv_bfloat16* __restrict__ qlo,
             const __nv_bfloat16* __restrict__ k1hi, const __nv_bfloat16* __restrict__ k1lo,
             const __nv_bfloat16* __restrict__ k2hi, const __nv_bfloat16* __restrict__ k2lo,
             const float* __restrict__ ll, const float* __restrict__ vv,
             const float* __restrict__ aa, const float* __restrict__ va,
             float* __restrict__ A)
{
    extern __shared__ char smem[];
    const uint32_t sb = smem_to_u32(smem);
    const int tid = threadIdx.x, wid = tid >> 5, lane = tid & 31;
    const int bh = blockIdx.z, l0 = blockIdx.y << 6, s0 = blockIdx.x << 7;
    const uint32_t oQh = 0, oQl = LG_QT, oK1h = 2*LG_QT, oK1l = 2*LG_QT + LG_KT,
                   oK2h = 2*LG_QT + 2*LG_KT, oK2l = 2*LG_QT + 3*LG_KT;

    {
        const __nv_bfloat16* qh = qhi + ((size_t)(bh * LQ + l0) << 6);
        const __nv_bfloat16* ql = qlo + ((size_t)(bh * LQ + l0) << 6);
#pragma unroll
        for (int i = tid; i < 512; i += 256) {
            int r = i >> 3, c = i & 7;
            uint32_t d = (uint32_t)(r * (LG_PAD*2) + c * 16);
            *(uint4*)(smem + oQh + d) = *(const uint4*)(qh + (r << 6) + (c << 3));
            *(uint4*)(smem + oQl + d) = *(const uint4*)(ql + (r << 6) + (c << 3));
        }
        const __nv_bfloat16* p1h = k1hi + ((size_t)(bh * SK + s0) << 6);
        const __nv_bfloat16* p1l = k1lo + ((size_t)(bh * SK + s0) << 6);
        const __nv_bfloat16* p2h = k2hi + ((size_t)(bh * SK + s0) << 6);
        const __nv_bfloat16* p2l = k2lo + ((size_t)(bh * SK + s0) << 6);
#pragma unroll
        for (int i = tid; i < 1024; i += 256) {
            int r = i >> 3, c = i & 7;
            uint32_t d = (uint32_t)(r * (LG_PAD*2) + c * 16);
            *(uint4*)(smem + oK1h + d) = *(const uint4*)(p1h + (r << 6) + (c << 3));
            *(uint4*)(smem + oK1l + d) = *(const uint4*)(p1l + (r << 6) + (c << 3));
            *(uint4*)(smem + oK2h + d) = *(const uint4*)(p2h + (r << 6) + (c << 3));
            *(uint4*)(smem + oK2l + d) = *(const uint4*)(p2l + (r << 6) + (c << 3));
        }
    }
    __syncthreads();

    const int wm = (wid & 1) << 5, wn = (wid >> 1) << 5;
    float lv[2][4][4] = {}, la[2][4][4] = {};
#pragma unroll
    for (int kk = 0; kk < 4; kk++) {
        const uint32_t coff = (uint32_t)(kk * 16 + ((lane >> 4) << 3)) * 2u;
        uint32_t af[2][4], alf[2][4];
#pragma unroll
        for (int mt = 0; mt < 2; mt++) {
            uint32_t ra = (uint32_t)((wm + mt * 16 + (lane & 15)) * LG_PAD) * 2u + coff;
            ldm_x4(af[mt],  sb + oQh + ra);
            ldm_x4(alf[mt], sb + oQl + ra);
        }
        uint32_t b1h[2][4], b1l[2][4], b2h[2][4], b2l[2][4];
#pragma unroll
        for (int ng = 0; ng < 2; ng++) {
            uint32_t rb = (uint32_t)((wn + ng * 16 + (lane & 15)) * LG_PAD) * 2u + coff;
            ldm_x4(b1h[ng], sb + oK1h + rb);
            ldm_x4(b1l[ng], sb + oK1l + rb);
            ldm_x4(b2h[ng], sb + oK2h + rb);
            ldm_x4(b2l[ng], sb + oK2l + rb);
        }
#pragma unroll
        for (int mt = 0; mt < 2; mt++)
#pragma unroll
            for (int nt = 0; nt < 4; nt++) {
                const int ng = nt >> 1, sel = nt & 1;
                mma16816(lv[mt][nt], af[mt],  b1h[ng][sel], b1h[ng][sel + 2]);
                mma16816(lv[mt][nt], af[mt],  b1l[ng][sel], b1l[ng][sel + 2]);
                mma16816(lv[mt][nt], alf[mt], b1h[ng][sel], b1h[ng][sel + 2]);
                mma16816(la[mt][nt], af[mt],  b2h[ng][sel], b2h[ng][sel + 2]);
                mma16816(la[mt][nt], af[mt],  b2l[ng][sel], b2l[ng][sel + 2]);
                mma16816(la[mt][nt], alf[mt], b2h[ng][sel], b2h[ng][sel + 2]);
            }
    }

    const int qr = lane >> 2, qc = (lane & 3) << 1;
    float vvc[8], aac[8], vac[8];
#pragma unroll
    for (int nt = 0; nt < 4; nt++)
#pragma unroll
        for (int j = 0; j < 2; j++) {
            int c = bh * SK + s0 + wn + nt * 8 + qc + j;
            vvc[nt*2+j] = __ldg(&vv[c]); aac[nt*2+j] = __ldg(&aa[c]); vac[nt*2+j] = __ldg(&va[c]);
        }
#pragma unroll
    for (int mt = 0; mt < 2; mt++)
#pragma unroll
        for (int half = 0; half < 2; half++) {
            int l = l0 + wm + mt * 16 + qr + (half << 3);
            float llr = __ldg(&ll[bh * LQ + l]);
            float* rowp = A + (((size_t)(bh * LQ + l)) << 10);
#pragma unroll
            for (int nt = 0; nt < 4; nt++) {
                float r2[2];
#pragma unroll
                for (int j = 0; j < 2; j++) {
                    float LV = lv[mt][nt][half * 2 + j];
                    float LA = la[mt][nt][half * 2 + j];
                    int ci = nt * 2 + j;
                    float det = llr * (vvc[ci] * aac[ci] - vac[ci] * vac[ci])
                              - LV * (LV * aac[ci] - LA * vac[ci])
                              + LA * (LV * vac[ci] - LA * vvc[ci]);
                    det = fmaxf(det, 1e-8f);
                    r2[j] = LV + LA - 1.5f * fast_sqrt(det);
                }
                *(float2*)&rowp[s0 + wn + nt * 8 + qc] = make_float2(r2[0], r2[1]);
            }
        }
}

// ---------------- warp-per-head softmax + head-average ----------------
__global__ void k_softmax_avg(const float* __restrict__ A, __nv_bfloat16* __restrict__ Phi,
                              __nv_bfloat16* __restrict__ Plo, float* __restrict__ avg)
{
    const int bl = blockIdx.x;               // 0..2047
    const int b = bl >> 9, l = bl & (LQ - 1);
    const int w = threadIdx.x >> 5, lane = threadIdx.x & 31;
    __shared__ float sp[8][SK];              // per-warp partial head sums (32 KB)

    float pacc[32];
#pragma unroll
    for (int i = 0; i < 32; i++) pacc[i] = 0.f;

#pragma unroll
    for (int hh = 0; hh < 2; hh++) {
        const int h = w + hh * 8;
        const size_t row = (size_t)(b * HDIM + h) * LQ + l;
        const float* p = A + (row << 10);
        float x[32];
#pragma unroll
        for (int j = 0; j < 8; j++) {
            float4 v = *(const float4*)(p + j * 128 + lane * 4);
            x[j*4+0] = v.x; x[j*4+1] = v.y; x[j*4+2] = v.z; x[j*4+3] = v.w;
        }
        float m = x[0];
#pragma unroll
        for (int i = 1; i < 32; i++) m = fmaxf(m, x[i]);
#pragma unroll
        for (int o = 16; o; o >>= 1) m = fmaxf(m, __shfl_xor_sync(0xffffffffu, m, o));
        float s = 0.f;
#pragma unroll
        for (int i = 0; i < 32; i++) { x[i] = fast_exp(x[i] - m); s += x[i]; }
#pragma unroll
        for (int o = 16; o; o >>= 1) s += __shfl_xor_sync(0xffffffffu, s, o);
        float inv = 1.0f / s;
#pragma unroll
        for (int j = 0; j < 8; j++) {
            float v0 = x[j*4+0] * inv, v1 = x[j*4+1] * inv;
            float v2 = x[j*4+2] * inv, v3 = x[j*4+3] * inv;
            pacc[j*4+0] += v0; pacc[j*4+1] += v1; pacc[j*4+2] += v2; pacc[j*4+3] += v3;
            __nv_bfloat16 h0 = __float2bfloat16(v0), h1 = __float2bfloat16(v1);
            __nv_bfloat16 h2 = __float2bfloat16(v2), h3 = __float2bfloat16(v3);
            __nv_bfloat16 l0 = __float2bfloat16(v0 - __bfloat162float(h0));
            __nv_bfloat16 l1 = __float2bfloat16(v1 - __bfloat162float(h1));
            __nv_bfloat16 l2 = __float2bfloat16(v2 - __bfloat162float(h2));
            __nv_bfloat16 l3 = __float2bfloat16(v3 - __bfloat162float(h3));
            size_t o = (row << 10) + j * 128 + lane * 4;
            ((__nv_bfloat162*)(Phi + o))[0] = __nv_bfloat162(h0, h1);
            ((__nv_bfloat162*)(Phi + o))[1] = __nv_bfloat162(h2, h3);
            ((__nv_bfloat162*)(Plo + o))[0] = __nv_bfloat162(l0, l1);
            ((__nv_bfloat162*)(Plo + o))[1] = __nv_bfloat162(l2, l3);
        }
    }

    if (avg) {
#pragma unroll
        for (int j = 0; j < 8; j++)
            *(float4*)&sp[w][j * 128 + lane * 4] = make_float4(pacc[j*4+0], pacc[j*4+1],
                                                               pacc[j*4+2], pacc[j*4+3]);
        __syncthreads();
        const int t = threadIdx.x;
        float4 a4;
        float* ap = (float*)&a4;
#pragma unroll
        for (int k = 0; k < 4; k++) {
            int pos = t * 4 + k;
            float acc = 0.f;
#pragma unroll
            for (int ww = 0; ww < 8; ww++) acc += sp[ww][pos];
            ap[k] = acc * (1.f / HDIM);
        }
        *(float4*)&avg[(((size_t)b * LQ + l) << 10) + t * 4] = a4;
    }
}

// ================== attn @ V + gate + split -> cb ==================
#define AV_PAD 72
#define AV_T (64 * AV_PAD * 2)
#define AV_STAGE (6 * AV_T)
#define AV_SMEM (2 * AV_STAGE)

__global__ void __launch_bounds__(256, 2)
k_av_mma(const __nv_bfloat16* __restrict__ athi, const __nv_bfloat16* __restrict__ atlo,
         const __nv_bfloat16* __restrict__ v1hi, const __nv_bfloat16* __restrict__ v1lo,
         const __nv_bfloat16* __restrict__ v2hi, const __nv_bfloat16* __restrict__ v2lo,
         const float* __restrict__ G1, const float* __restrict__ G2,
         __nv_bfloat16* __restrict__ cbhi, __nv_bfloat16* __restrict__ cblo)
{
    extern __shared__ char smem[];
    const uint32_t sb = smem_to_u32(smem);
    const int tid = threadIdx.x, wid = tid >> 5, lane = tid & 31;
    const int bh = blockIdx.y, l0 = blockIdx.x << 6;
    const int wm = (wid & 1) << 5, wn = (wid >> 1) << 4;

    float acc1[2][2][4] = {}, acc2[2][2][4] = {};

#define AV_LOAD(stg, s0k) do { \
    _Pragma("unroll") \
    for (int i = 0; i < 12; i++) { \
        int id = (i << 8) + tid; \
        int a = id >> 9; \
        int rr = (id >> 3) & 63; \
        int c = id & 7; \
        const __nv_bfloat16* g; \
        if (a < 2) g = (a ? atlo : athi) + (((size_t)(bh * LQ + l0 + rr)) << 10) + (s0k) + (c << 3); \
        else { \
            const __nv_bfloat16* vb = (a == 2) ? v1hi : (a == 3) ? v1lo : (a == 4) ? v2hi : v2lo; \
            g = vb + (((size_t)(bh * SK + (s0k) + rr)) << 6) + (c << 3); \
        } \
        uint32_t sa = sb + (uint32_t)(stg) * AV_STAGE + (uint32_t)a * AV_T + (uint32_t)(rr * (AV_PAD*2) + c * 16); \
        CP_ASYNC16(sa, g); \
    } \
    CP_COMMIT(); \
} while (0)

    AV_LOAD(0, 0);

    for (int ch = 0; ch < 16; ch++) {
        const int stg = ch & 1;
        if (ch + 1 < 16) { AV_LOAD(stg ^ 1, (ch + 1) << 6); CP_WAIT(1); }
        else             { CP_WAIT(0); }
        __syncthreads();

        const uint32_t st = sb + (uint32_t)stg * AV_STAGE;
#pragma unroll
        for (int kk = 0; kk < 4; kk++) {
            const uint32_t coff = (uint32_t)(kk * 16 + ((lane >> 4) << 3)) * 2u;
            uint32_t af[2][4], alf[2][4];
#pragma unroll
            for (int mt = 0; mt < 2; mt++) {
                uint32_t ra = (uint32_t)((wm + mt * 16 + (lane & 15)) * AV_PAD) * 2u + coff;
                ldm_x4(af[mt],  st + ra);
                ldm_x4(alf[mt], st + AV_T + ra);
            }
            uint32_t bv1h[4], bv1l[4], bv2h[4], bv2l[4];
            {
                uint32_t rb = (uint32_t)((kk * 16 + (lane & 15)) * AV_PAD + wn + ((lane >> 4) << 3)) * 2u;
                ldm_x4_t(bv1h, st + 2 * AV_T + rb);
                ldm_x4_t(bv1l, st + 3 * AV_T + rb);
                ldm_x4_t(bv2h, st + 4 * AV_T + rb);
                ldm_x4_t(bv2l, st + 5 * AV_T + rb);
            }
#pragma unroll
            for (int mt = 0; mt < 2; mt++)
#pragma unroll
                for (int nt = 0; nt < 2; nt++) {
                    mma16816(acc1[mt][nt], af[mt],  bv1h[nt*2], bv1h[nt*2+1]);
                    mma16816(acc1[mt][nt], af[mt],  bv1l[nt*2], bv1l[nt*2+1]);
                    mma16816(acc1[mt][nt], alf[mt], bv1h[nt*2], bv1h[nt*2+1]);
                    mma16816(acc2[mt][nt], af[mt],  bv2h[nt*2], bv2h[nt*2+1]);
                    mma16816(acc2[mt][nt], af[mt],  bv2l[nt*2], bv2l[nt*2+1]);
                    mma16816(acc2[mt][nt], alf[mt], bv2h[nt*2], bv2h[nt*2+1]);
                }
        }
        __syncthreads();
    }

    const int qr = lane >> 2, qc = (lane & 3) << 1;
    const int b_ = bh >> 4, h_ = bh & 15;
#pragma unroll
    for (int mt = 0; mt < 2; mt++)
#pragma unroll
        for (int half = 0; half < 2; half++) {
            int l = l0 + wm + mt * 16 + qr + (half << 3);
            const float* g1r = G1 + ((size_t)(bh * LQ + l)) * DHD;
            const float* g2r = G2 + ((size_t)(bh * LQ + l)) * DHD;
            size_t rowo = ((size_t)(l * BDIM + b_)) << 10;
#pragma unroll
            for (int nt = 0; nt < 2; nt++) {
                int d = wn + nt * 8 + qc;
                float2 g1 = *(const float2*)&g1r[d];
                float2 g2 = *(const float2*)&g2r[d];
                float c0 = (acc1[mt][nt][half*2+0] * g1.x + acc2[mt][nt][half*2+0] * g2.x) * 0.5f;
                float c1 = (acc1[mt][nt][half*2+1] * g1.y + acc2[mt][nt][half*2+1] * g2.y) * 0.5f;
                __nv_bfloat16 h0 = __float2bfloat16(c0), h1 = __float2bfloat16(c1);
                __nv_bfloat16 l0b = __float2bfloat16(c0 - __bfloat162float(h0));
                __nv_bfloat16 l1b = __float2bfloat16(c1 - __bfloat162float(h1));
                size_t o = rowo + h_ * DHD + d;
                *(__nv_bfloat162*)&cbhi[o] = __nv_bfloat162(h0, h1);
                *(__nv_bfloat162*)&cblo[o] = __nv_bfloat162(l0b, l1b);
            }
        }
#undef AV_LOAD
}

// ---------------- launch ----------------
extern "C" void kernel_launch(void* const* d_in, const int* in_sizes, int n_in,
                              void* d_out, int out_size)
{
    const float* query = (const float*)d_in[0];
    const float* mod1  = (const float*)d_in[1];
    const float* mod2  = (const float*)d_in[2];
    WPtrs wp;
    const float* bi[8];
    for (int i = 0; i < 8; i++) {
        wp.p[i] = (const float*)d_in[3 + 2*i];
        bi[i]   = (const float*)d_in[4 + 2*i];
    }
    float* out = (float*)d_out;
    float* avg_out = ((size_t)out_size >= 2ULL * LQ * BDIM * EDIM)
                   ? out + (size_t)LQ * BDIM * EDIM : nullptr;

    float *G1h, *G2h, *ll, *vv, *aa, *va, *Attn;
    cudaGetSymbolAddress((void**)&G1h, g_G1h);
    cudaGetSymbolAddress((void**)&G2h, g_G2h);
    cudaGetSymbolAddress((void**)&ll,  g_ll);
    cudaGetSymbolAddress((void**)&vv,  g_vv);
    cudaGetSymbolAddress((void**)&aa,  g_aa);
    cudaGetSymbolAddress((void**)&va,  g_va);
    cudaGetSymbolAddress((void**)&Attn, g_Attn);

    __nv_bfloat16 *qhi,*qlo,*k1hi,*k1lo,*k2hi,*k2lo,*v1hi,*v1lo,*v2hi,*v2lo,*athi,*atlo;
    __nv_bfloat16 *xq_hi,*xq_lo,*m1_hi,*m1_lo,*m2_hi,*m2_lo,*cb_hi,*cb_lo,*wt_hi,*wt_lo;
    cudaGetSymbolAddress((void**)&qhi,  g_q_hi);  cudaGetSymbolAddress((void**)&qlo,  g_q_lo);
    cudaGetSymbolAddress((void**)&k1hi, g_k1_hi); cudaGetSymbolAddress((void**)&k1lo, g_k1_lo);
    cudaGetSymbolAddress((void**)&k2hi, g_k2_hi); cudaGetSymbolAddress((void**)&k2lo, g_k2_lo);
    cudaGetSymbolAddress((void**)&v1hi, g_v1_hi); cudaGetSymbolAddress((void**)&v1lo, g_v1_lo);
    cudaGetSymbolAddress((void**)&v2hi, g_v2_hi); cudaGetSymbolAddress((void**)&v2lo, g_v2_lo);
    cudaGetSymbolAddress((void**)&athi, g_at_hi); cudaGetSymbolAddress((void**)&atlo, g_at_lo);
    cudaGetSymbolAddress((void**)&xq_hi, g_xq_hi); cudaGetSymbolAddress((void**)&xq_lo, g_xq_lo);
    cudaGetSymbolAddress((void**)&m1_hi, g_m1_hi); cudaGetSymbolAddress((void**)&m1_lo, g_m1_lo);
    cudaGetSymbolAddress((void**)&m2_hi, g_m2_hi); cudaGetSymbolAddress((void**)&m2_lo, g_m2_lo);
    cudaGetSymbolAddress((void**)&cb_hi, g_cb_hi); cudaGetSymbolAddress((void**)&cb_lo, g_cb_lo);
    cudaGetSymbolAddress((void**)&wt_hi, g_wt_hi); cudaGetSymbolAddress((void**)&wt_lo, g_wt_lo);

    cudaFuncSetAttribute(gemm_mma<128>, cudaFuncAttributeMaxDynamicSharedMemorySize, GM_SMEM_128);
    cudaFuncSetAttribute(gemm_mma<64>,  cudaFuncAttributeMaxDynamicSharedMemorySize, GM_SMEM_64);
    cudaFuncSetAttribute(k_logits_mma,  cudaFuncAttributeMaxDynamicSharedMemorySize, LG_SMEM);
    cudaFuncSetAttribute(k_av_mma,      cudaFuncAttributeMaxDynamicSharedMemorySize, AV_SMEM);

    k_split_all<<<10240, 256>>>(query, mod1, mod2, xq_hi, xq_lo, m1_hi, m1_lo, m2_hi, m2_lo);
    k_wsplit_all<<<dim3(32, 32, 8), dim3(32, 8)>>>(wp, wt_hi, wt_lo);

    size_t WSZ = (size_t)1024*1024;

    // ---- ALL 7 projections in ONE TM=128 launch ----
    {
        GemmBatch gb = {};
        const __nv_bfloat16* As[4]  = {m1_hi, m2_hi, m1_hi, m2_hi};
        const __nv_bfloat16* Als[4] = {m1_lo, m2_lo, m1_lo, m2_lo};
        __nv_bfloat16* oh[4] = {k1hi, k2hi, v1hi, v2hi};
        __nv_bfloat16* ol[4] = {k1lo, k2lo, v1lo, v2lo};
        for (int z = 0; z < 4; z++) {
            gb.Ahi[z] = As[z]; gb.Alo[z] = Als[z];
            gb.Bhi[z] = wt_hi + (size_t)(1 + z) * WSZ;
            gb.Blo[z] = wt_lo + (size_t)(1 + z) * WSZ;
            gb.bias[z] = bi[1 + z];
            gb.outHi[z] = oh[z]; gb.outLo[z] = ol[z];
            gb.outF[z] = nullptr;
            gb.scale[z] = 1.f; gb.mode[z] = 0; gb.rows[z] = 4096; gb.npos[z] = SK;
        }
        gb.Ahi[4] = gb.Ahi[5] = gb.Ahi[6] = xq_hi;
        gb.Alo[4] = gb.Alo[5] = gb.Alo[6] = xq_lo;
        gb.Bhi[4] = wt_hi + 0*WSZ; gb.Blo[4] = wt_lo + 0*WSZ; gb.bias[4] = bi[0];
        gb.Bhi[5] = wt_hi + 5*WSZ; gb.Blo[5] = wt_lo + 5*WSZ; gb.bias[5] = bi[5];
        gb.Bhi[6] = wt_hi + 6*WSZ; gb.Blo[6] = wt_lo + 6*WSZ; gb.bias[6] = bi[6];
        gb.outHi[4] = qhi; gb.outLo[4] = qlo; gb.outF[4] = nullptr;
        gb.scale[4] = 0.125f; gb.mode[4] = 0; gb.rows[4] = 2048; gb.npos[4] = LQ;
        gb.outF[5] = G1h; gb.scale[5] = 1.f; gb.mode[5] = 1; gb.rows[5] = 2048; gb.npos[5] = LQ;
        gb.outF[6] = G2h; gb.scale[6] = 1.f; gb.mode[6] = 1; gb.rows[6] = 2048; gb.npos[6] = LQ;
        gemm_mma<128><<<dim3(8, 32, 7), 256, GM_SMEM_128>>>(gb);
    }

    // fused stats (q + k1/k2 in one launch)
    k_stats<<<((BH*LQ + BH*SK) * 32 + 255) / 256, 256>>>(
        qhi, qlo, k1hi, k1lo, k2hi, k2lo, ll, vv, aa, va);

    k_logits_mma<<<dim3(SK/128, LQ/64, BH), 256, LG_SMEM>>>(
        qhi, qlo, k1hi, k1lo, k2hi, k2lo, ll, vv, aa, va, Attn);

    k_softmax_avg<<<BDIM*LQ, 256>>>(Attn, athi, atlo, avg_out);

    k_av_mma<<<dim3(LQ/64, BH), 256, AV_SMEM>>>(athi, atlo, v1hi, v1lo, v2hi, v2lo,
                                                G1h, G2h, cb_hi, cb_lo);

    // ---- output projection ----
    {
        GemmBatch gb = {};
        gb.Ahi[0] = cb_hi; gb.Alo[0] = cb_lo;
        gb.Bhi[0] = wt_hi + 7*WSZ; gb.Blo[0] = wt_lo + 7*WSZ; gb.bias[0] = bi[7];
        gb.outF[0] = out; gb.scale[0] = 1.f; gb.mode[0] = 2;
        gb.rows[0] = 2048; gb.npos[0] = LQ;
        gemm_mma<64><<<dim3(8, 32, 1), 256, GM_SMEM_64>>>(gb);
    }
}